// round 14
// baseline (speedup 1.0000x reference)
#include <cuda_runtime.h>
#include <cuda_bf16.h>
#include <math.h>
#include <stdint.h>

#define Bb   32
#define Ss   256
#define Ee   768
#define Hh   512
#define Cc   30
#define IN0v 770
#define Gg   2048
#define SB   (Ss*Bb)          /* 8192 */
#define LSTRIDE (Bb*Ss*Ee)    /* hidden_states layer stride */
#define NCTA_DIR 128

// ---------------- scratch (device globals; no runtime allocation) ------------
__device__ float g_x0[SB*IN0v];        // [S][B][770]  layer-0 input features
__device__ float g_xw[2][SB*Gg];       // [dir][S][B][2048] precomputed input proj
__device__ float g_seq0[SB*1024];      // [S][B][1024] layer-0 output
__device__ float g_seq1[SB*1024];      // [S][B][1024] layer-1 output
__device__ float g_hT[2*2*Hh*Bb];      // [dir][parity][h][b] double-buffered h
__device__ float g_mw[Bb*Ss];          // mean over E per (b,s)
__device__ float g_mp[Bb];             // mean at predicate position per b
__device__ unsigned g_cnt[2];          // per-direction barrier arrive count
__device__ unsigned g_gen[2];          // per-direction barrier generation
// bf16 hi/lo staging for tensor-core GEMMs (Kp <= 1024)
__device__ __nv_bfloat16 g_Ah[SB*1024];
__device__ __nv_bfloat16 g_Al[SB*1024];
__device__ __nv_bfloat16 g_Wh[2][Gg*1024];
__device__ __nv_bfloat16 g_Wl[2][Gg*1024];

// ---------------- feature build ----------------------------------------------
__global__ void feat_mean_kernel(const float* __restrict__ hs)
{
    int bs = blockIdx.x;              // b*Ss + s
    int b = bs / Ss, s = bs % Ss;
    const float* p = hs + ((size_t)b*Ss + s)*Ee;
    size_t xb = ((size_t)s*Bb + b)*IN0v;
    float lsum = 0.f;
    for (int e = threadIdx.x; e < Ee; e += 256){
        float v = (p[e] + p[e+LSTRIDE] + p[e+2*LSTRIDE] + p[e+3*LSTRIDE])*0.25f;
        g_x0[xb + e] = v;
        lsum += v;
    }
    __shared__ float sred[256];
    sred[threadIdx.x] = lsum;
    __syncthreads();
    for (int st = 128; st > 0; st >>= 1){
        if (threadIdx.x < st) sred[threadIdx.x] += sred[threadIdx.x + st];
        __syncthreads();
    }
    if (threadIdx.x == 0) g_mw[bs] = sred[0]*(1.f/768.f);
}

__global__ void pred_kernel(const int* __restrict__ pred)
{
    int b = threadIdx.x;
    if (b >= Bb) return;
    const int* row = pred + b*Ss;
    int best = row[0], idx = 0;
    for (int s = 1; s < Ss; s++){ int v = row[s]; if (v > best){ best = v; idx = s; } }
    g_mp[b] = g_mw[b*Ss + idx];
}

__global__ void fill_kernel(const int* __restrict__ roles)
{
    int t = blockIdx.x*blockDim.x + threadIdx.x;
    if (t >= Bb*Ss) return;
    int b = t / Ss, s = t % Ss;
    int r = roles[t];
    size_t xb = ((size_t)s*Bb + b)*IN0v;
    g_x0[xb + Ee]     = g_mw[t] - g_mp[b];
    g_x0[xb + Ee + 1] = (r != 0 && r != -100) ? 1.f : 0.f;
}

// ---------------- bf16 hi/lo conversion ---------------------------------------
__global__ void convA_kernel(int srcSel, int K, int Kp)
{
    const float* A = srcSel ? g_seq0 : g_x0;
    int idx = blockIdx.x*256 + threadIdx.x;
    if (idx >= SB*Kp) return;
    int m = idx / Kp, k = idx - m*Kp;
    float v = (k < K) ? A[(size_t)m*K + k] : 0.f;
    __nv_bfloat16 h = __float2bfloat16(v);
    g_Ah[idx] = h;
    g_Al[idx] = __float2bfloat16(v - __bfloat162float(h));
}

__global__ void convW_kernel(const float* __restrict__ W, int K, int Kp, int dir)
{
    int idx = blockIdx.x*256 + threadIdx.x;
    if (idx >= Gg*Kp) return;
    int n = idx / Kp, k = idx - n*Kp;
    float v = (k < K) ? W[(size_t)n*K + k] : 0.f;
    __nv_bfloat16 h = __float2bfloat16(v);
    g_Wh[dir][idx] = h;
    g_Wl[dir][idx] = __float2bfloat16(v - __bfloat162float(h));
}

// ---------------- tensor-core GEMM  C = A*W^T + (b1+b2),  bf16x3 --------------
#define MMA16816(C, A0,A1,A2,A3, B0,B1) \
    asm volatile("mma.sync.aligned.m16n8k16.row.col.f32.bf16.bf16.f32 " \
        "{%0,%1,%2,%3}, {%4,%5,%6,%7}, {%8,%9}, {%0,%1,%2,%3};" \
        : "+f"((C)[0]),"+f"((C)[1]),"+f"((C)[2]),"+f"((C)[3]) \
        : "r"(A0),"r"(A1),"r"(A2),"r"(A3),"r"(B0),"r"(B1))

__global__ __launch_bounds__(256,2) void tc_gemm_bias(
    int dir, const float* __restrict__ b1, const float* __restrict__ b2, int Kp)
{
    __shared__ uint32_t Ah_s[128][8], Al_s[128][8];
    __shared__ uint32_t Wh_s[128][8], Wl_s[128][8];

    float* Cmat = g_xw[dir];
    const __nv_bfloat16* Whg = g_Wh[dir];
    const __nv_bfloat16* Wlg = g_Wl[dir];

    int m0 = blockIdx.y*128, n0 = blockIdx.x*128;
    int tid = threadIdx.x;
    int lane = tid & 31, wid = tid >> 5;
    int g = lane >> 2, tg = lane & 3;
    int m_w = (wid & 1)*64, n_w = (wid >> 1)*32;

    int lrow = tid >> 1, lhw = tid & 1;   // loader: row, 16B-half

    float c[4][4][4];
#pragma unroll
    for (int mi=0;mi<4;mi++)
#pragma unroll
        for (int ni=0;ni<4;ni++)
#pragma unroll
            for (int q=0;q<4;q++) c[mi][ni][q] = 0.f;

    int steps = Kp >> 4;
    for (int s = 0; s < steps; s++){
        size_t aoff = (size_t)(m0 + lrow)*Kp + s*16;
        size_t woff = (size_t)(n0 + lrow)*Kp + s*16;
        *(uint4*)&Ah_s[lrow][lhw*4] = ((const uint4*)(g_Ah + aoff))[lhw];
        *(uint4*)&Al_s[lrow][lhw*4] = ((const uint4*)(g_Al + aoff))[lhw];
        *(uint4*)&Wh_s[lrow][lhw*4] = ((const uint4*)(Whg  + woff))[lhw];
        *(uint4*)&Wl_s[lrow][lhw*4] = ((const uint4*)(Wlg  + woff))[lhw];
        __syncthreads();

        uint32_t af[4][8];
#pragma unroll
        for (int mi=0;mi<4;mi++){
            int r0 = m_w + mi*16 + g;
            af[mi][0] = Ah_s[r0  ][tg];   af[mi][1] = Ah_s[r0+8][tg];
            af[mi][2] = Ah_s[r0  ][tg+4]; af[mi][3] = Ah_s[r0+8][tg+4];
            af[mi][4] = Al_s[r0  ][tg];   af[mi][5] = Al_s[r0+8][tg];
            af[mi][6] = Al_s[r0  ][tg+4]; af[mi][7] = Al_s[r0+8][tg+4];
        }

#pragma unroll
        for (int ni=0;ni<4;ni++){
            int rn = n_w + ni*8 + g;
            uint32_t bh0 = Wh_s[rn][tg], bh1 = Wh_s[rn][tg+4];
            uint32_t bl0 = Wl_s[rn][tg], bl1 = Wl_s[rn][tg+4];
#pragma unroll
            for (int mi=0;mi<4;mi++){
                MMA16816(c[mi][ni], af[mi][0],af[mi][1],af[mi][2],af[mi][3], bh0,bh1);
                MMA16816(c[mi][ni], af[mi][0],af[mi][1],af[mi][2],af[mi][3], bl0,bl1);
                MMA16816(c[mi][ni], af[mi][4],af[mi][5],af[mi][6],af[mi][7], bh0,bh1);
            }
        }
        __syncthreads();
    }

#pragma unroll
    for (int mi=0;mi<4;mi++){
#pragma unroll
        for (int ni=0;ni<4;ni++){
            int m = m0 + m_w + mi*16 + g;
            int n = n0 + n_w + ni*8 + tg*2;
            float bb0 = b1[n] + b2[n];
            float bb1 = b1[n+1] + b2[n+1];
            float2 v0 = { c[mi][ni][0] + bb0, c[mi][ni][1] + bb1 };
            float2 v1 = { c[mi][ni][2] + bb0, c[mi][ni][3] + bb1 };
            *(float2*)&Cmat[(size_t)m*Gg + n]     = v0;
            *(float2*)&Cmat[(size_t)(m+8)*Gg + n] = v1;
        }
    }
}

// ---------------- persistent bidirectional LSTM layer ------------------------
__device__ __forceinline__ float sigf(float x){ return 1.f/(1.f + expf(-x)); }

// R11 flat barrier (measured-good); tree version regressed in R12.
__device__ __forceinline__ void grid_bar(int dir, unsigned* s_gen)
{
    __syncthreads();
    if (threadIdx.x == 0){
        __threadfence();
        unsigned g0 = *s_gen;
        if (atomicAdd(&g_cnt[dir], 1u) == NCTA_DIR - 1u){
            g_cnt[dir] = 0u;
            __threadfence();
            atomicAdd(&g_gen[dir], 1u);
        } else {
            while (atomicAdd(&g_gen[dir], 0u) == g0) { __nanosleep(64); }
        }
        __threadfence();
        *s_gen = g0 + 1u;
    }
    __syncthreads();
}

// packed fp32x2 FMA: acc = a*b + acc  (per-lane IEEE fp32, sm_100+)
#define FMA_F32X2(acc, a, b) \
    asm("fma.rn.f32x2 %0, %1, %2, %0;" : "+l"(acc) : "l"(a), "l"(b))
#define PACK_F32X2_(d, lo, hi) \
    asm("mov.b64 %0, {%1, %2};" : "=l"(d) : "f"(lo), "f"(hi))
#define UNPACK_F32X2_(lo, hi, s) \
    asm("mov.b64 {%0, %1}, %2;" : "=f"(lo), "=f"(hi) : "l"(s))

// grid = 256 CTAs (128 per direction, 2 per SM), 256 threads.
// Whh stored in SMEM as duplicated float2 pairs so the inner loop is pure
// FFMA2: per k = 1 LDS.128 (h) + 2 LDS.128 (w pairs) + 2 packs + 8 FFMA2.
__global__ __launch_bounds__(256,2) void lstm_layer_kernel(
    const float* __restrict__ Whh_f, const float* __restrict__ Whh_b, int layer)
{
    extern __shared__ float sm[];
    float2* W2_s = (float2*)sm;          // [512][16] float2 (dup pairs) = 16384 floats
    float*  hp_s = sm + 16384;           // [128][32] h chunk = 4096 floats
    float*  red  = sm + 20480;           // 8 splits x 16 cols x 33 = 4224 floats
    __shared__ unsigned s_gen;

    int dir = blockIdx.x >> 7;
    int cid = blockIdx.x & 127;
    int hc0 = cid * 4;
    int tid = threadIdx.x;
    const float* Whh = dir ? Whh_b : Whh_f;
    const float* xw  = g_xw[dir];
    float* outseq = layer ? g_seq1 : g_seq0;

    if (tid == 0) s_gen = g_gen[dir];

    // Load Whh slice as duplicated pairs: W2_s[k][q*4+j] = (w, w)
    for (int idx = tid; idx < 512*16; idx += 256){
        int col = idx & 15, k = idx >> 4;
        int q = col >> 2, j = col & 3;
        float w = Whh[(size_t)(q*512 + hc0 + j)*512 + k];
        W2_s[k*16 + col] = make_float2(w, w);
    }
    if (tid < 128){
        int j = tid >> 5, b = tid & 31;
        g_hT[(dir*2 + 0)*Hh*Bb + (hc0+j)*Bb + b] = 0.f;
    }
    float c_reg = 0.f;
    int jj = (tid >> 5) & 3, bbn = tid & 31;

    int kg = tid >> 5;                   // 8 k-split groups
    int t2 = tid & 31;
    int bq = (t2 & 7) * 4;               // batch quad
    int gq = (t2 >> 3) * 4;              // gate-col quad (0,4,8,12)

    int colR[2], bIR[2], xoffR[2];
#pragma unroll
    for (int r = 0; r < 2; r++){
        int idx = tid + 256*r;
        colR[r] = idx >> 5;
        bIR[r]  = idx & 31;
        int q = colR[r] >> 2, j = colR[r] & 3;
        xoffR[r] = q*512 + hc0 + j;
    }

    grid_bar(dir, &s_gen);

    for (int t = 0; t < Ss; t++){
        int s = dir ? (Ss - 1 - t) : t;
        const float* xwt = xw + (size_t)s*Bb*Gg;

        float xpre[2];
#pragma unroll
        for (int r = 0; r < 2; r++)
            xpre[r] = __ldg(&xwt[(size_t)bIR[r]*Gg + xoffR[r]]);

        unsigned long long acc2[4][2];
#pragma unroll
        for (int i=0;i<4;i++){ acc2[i][0] = 0ull; acc2[i][1] = 0ull; }

        const float4* hsrc4 = (const float4*)(g_hT + (dir*2 + (t & 1))*Hh*Bb);

#pragma unroll
        for (int chunk = 0; chunk < 4; chunk++){
            // stage 128-k chunk of h_prev (4 float4 per thread)
#pragma unroll
            for (int r = 0; r < 4; r++)
                ((float4*)hp_s)[tid + 256*r] = hsrc4[chunk*1024 + tid + 256*r];
            __syncthreads();

            const float*  hpk = hp_s + kg*16*32;
            const float2* wpk = W2_s + (chunk*128 + kg*16)*16 + gq;
#pragma unroll
            for (int k = 0; k < 16; k++){
                float4 hv = *reinterpret_cast<const float4*>(hpk + (k<<5) + bq);
                unsigned long long h01, h23;
                PACK_F32X2_(h01, hv.x, hv.y);
                PACK_F32X2_(h23, hv.z, hv.w);
                ulonglong2 wA = *reinterpret_cast<const ulonglong2*>(wpk + k*16);
                ulonglong2 wB = *reinterpret_cast<const ulonglong2*>(wpk + k*16 + 2);
                FMA_F32X2(acc2[0][0], wA.x, h01); FMA_F32X2(acc2[0][1], wA.x, h23);
                FMA_F32X2(acc2[1][0], wA.y, h01); FMA_F32X2(acc2[1][1], wA.y, h23);
                FMA_F32X2(acc2[2][0], wB.x, h01); FMA_F32X2(acc2[2][1], wB.x, h23);
                FMA_F32X2(acc2[3][0], wB.y, h01); FMA_F32X2(acc2[3][1], wB.y, h23);
            }
            __syncthreads();   // protect hp_s before restage
        }

        // unpack accumulators into red (same slots as scalar version)
#pragma unroll
        for (int gi=0; gi<4; gi++){
#pragma unroll
            for (int p=0; p<2; p++){
                float lo, hi;
                UNPACK_F32X2_(lo, hi, acc2[gi][p]);
                red[kg*528 + (gq+gi)*33 + (bq + 2*p)]     = lo;
                red[kg*528 + (gq+gi)*33 + (bq + 2*p + 1)] = hi;
            }
        }
        __syncthreads();

#pragma unroll
        for (int r = 0; r < 2; r++){
            int col = colR[r], bI = bIR[r];
            float v = xpre[r];
#pragma unroll
            for (int g2 = 0; g2 < 8; g2++)
                v += red[g2*528 + col*33 + bI];
            red[col*33 + bI] = v;
        }
        __syncthreads();

        if (tid < 128){
            float iv = red[( 0 + jj)*33 + bbn];
            float fv = red[( 4 + jj)*33 + bbn];
            float gv = red[( 8 + jj)*33 + bbn];
            float ov = red[(12 + jj)*33 + bbn];
            float cnew = sigf(fv)*c_reg + sigf(iv)*tanhf(gv);
            float hnew = sigf(ov)*tanhf(cnew);
            c_reg = cnew;
            g_hT[(dir*2 + ((t+1)&1))*Hh*Bb + (hc0+jj)*Bb + bbn] = hnew;
            outseq[((size_t)s*Bb + bbn)*1024 + dir*512 + hc0 + jj] = hnew;
        }

        grid_bar(dir, &s_gen);
    }
}

// ---------------- output projection [8192,1024] x [1024,30] ------------------
__global__ void out_proj_kernel(const float* __restrict__ Wout,
                                const float* __restrict__ bout,
                                float* __restrict__ out)
{
    int gw = (blockIdx.x*blockDim.x + threadIdx.x) >> 5;
    int lane = threadIdx.x & 31;
    if (gw >= SB) return;
    const float* row = g_seq1 + (size_t)gw*1024;
    float xv[32];
#pragma unroll
    for (int i=0;i<32;i++) xv[i] = row[lane + 32*i];
    int s = gw >> 5, b = gw & 31;
    float* orow = out + ((size_t)b*Ss + s)*Cc;
    for (int c = 0; c < Cc; c++){
        const float* w = Wout + c*1024;
        float acc = 0.f;
#pragma unroll
        for (int i=0;i<32;i++) acc = fmaf(xv[i], w[lane + 32*i], acc);
#pragma unroll
        for (int off=16; off; off>>=1) acc += __shfl_xor_sync(0xffffffffu, acc, off);
        if (lane == 0) orow[c] = acc + bout[c];
    }
}

// ---------------- launch ------------------------------------------------------
extern "C" void kernel_launch(void* const* d_in, const int* in_sizes, int n_in,
                              void* d_out, int out_size)
{
    const float* hs     = (const float*)d_in[0];
    const int*   roles  = (const int*)  d_in[1];
    const int*   preds  = (const int*)  d_in[2];
    const float* Wih0f  = (const float*)d_in[3];
    const float* Whh0f  = (const float*)d_in[4];
    const float* bih0f  = (const float*)d_in[5];
    const float* bhh0f  = (const float*)d_in[6];
    const float* Wih0b  = (const float*)d_in[7];
    const float* Whh0b  = (const float*)d_in[8];
    const float* bih0b  = (const float*)d_in[9];
    const float* bhh0b  = (const float*)d_in[10];
    const float* Wih1f  = (const float*)d_in[11];
    const float* Whh1f  = (const float*)d_in[12];
    const float* bih1f  = (const float*)d_in[13];
    const float* bhh1f  = (const float*)d_in[14];
    const float* Wih1b  = (const float*)d_in[15];
    const float* Whh1b  = (const float*)d_in[16];
    const float* bih1b  = (const float*)d_in[17];
    const float* bhh1b  = (const float*)d_in[18];
    const float* Wout   = (const float*)d_in[19];
    const float* bout   = (const float*)d_in[20];
    float* out = (float*)d_out;

    const size_t lsm = (16384 + 4096 + 8*528) * sizeof(float);   // 98816
    cudaFuncSetAttribute(lstm_layer_kernel,
                         cudaFuncAttributeMaxDynamicSharedMemorySize, (int)lsm);

    feat_mean_kernel<<<SB, 256>>>(hs);
    pred_kernel<<<1, 32>>>(preds);
    fill_kernel<<<(Bb*Ss + 255)/256, 256>>>(roles);

    dim3 gproj(Gg/128, SB/128);   // (16, 64)

    // ---- layer 0: Kp = 784 ----
    {
        const int K = IN0v, Kp = 784;
        convA_kernel<<<(SB*Kp + 255)/256, 256>>>(0, K, Kp);
        convW_kernel<<<(Gg*Kp + 255)/256, 256>>>(Wih0f, K, Kp, 0);
        convW_kernel<<<(Gg*Kp + 255)/256, 256>>>(Wih0b, K, Kp, 1);
        tc_gemm_bias<<<gproj, 256>>>(0, bih0f, bhh0f, Kp);
        tc_gemm_bias<<<gproj, 256>>>(1, bih0b, bhh0b, Kp);
    }
    lstm_layer_kernel<<<256, 256, lsm>>>(Whh0f, Whh0b, 0);

    // ---- layer 1: Kp = 1024 ----
    {
        const int K = 1024, Kp = 1024;
        convA_kernel<<<(SB*Kp + 255)/256, 256>>>(1, K, Kp);
        convW_kernel<<<(Gg*Kp + 255)/256, 256>>>(Wih1f, K, Kp, 0);
        convW_kernel<<<(Gg*Kp + 255)/256, 256>>>(Wih1b, K, Kp, 1);
        tc_gemm_bias<<<gproj, 256>>>(0, bih1f, bhh1f, Kp);
        tc_gemm_bias<<<gproj, 256>>>(1, bih1b, bhh1b, Kp);
    }
    lstm_layer_kernel<<<256, 256, lsm>>>(Whh1f, Whh1b, 1);

    out_proj_kernel<<<(SB*32 + 255)/256, 256>>>(Wout, bout, out);
}

// round 16
// speedup vs baseline: 1.2089x; 1.2089x over previous
#include <cuda_runtime.h>
#include <cuda_bf16.h>
#include <math.h>
#include <stdint.h>

#define Bb   32
#define Ss   256
#define Ee   768
#define Hh   512
#define Cc   30
#define IN0v 770
#define Gg   2048
#define SB   (Ss*Bb)          /* 8192 */
#define LSTRIDE (Bb*Ss*Ee)    /* hidden_states layer stride */
#define NCTA_DIR 128

// ---------------- scratch (device globals; no runtime allocation) ------------
__device__ float g_x0[SB*IN0v];        // [S][B][770]  layer-0 input features
__device__ float g_xw[2][SB*Gg];       // [dir][S][B][2048] precomputed input proj
__device__ float g_seq0[SB*1024];      // [S][B][1024] layer-0 output
__device__ float g_seq1[SB*1024];      // [S][B][1024] layer-1 output
__device__ float g_mw[Bb*Ss];          // mean over E per (b,s)
__device__ float g_mp[Bb];             // mean at predicate position per b
__device__ unsigned g_cnt[2];          // per-direction barrier arrive count
__device__ unsigned g_gen[2];          // per-direction barrier generation
// h state as bf16 hi/lo, [dir][parity][batch][k]  (B operand of the recurrence mma)
__device__ __nv_bfloat16 g_hbh[2][2][Bb*Hh];
__device__ __nv_bfloat16 g_hbl[2][2][Bb*Hh];
// bf16 hi/lo staging for input-projection tensor-core GEMMs (Kp <= 1024)
__device__ __nv_bfloat16 g_Ah[SB*1024];
__device__ __nv_bfloat16 g_Al[SB*1024];
__device__ __nv_bfloat16 g_Wh[2][Gg*1024];
__device__ __nv_bfloat16 g_Wl[2][Gg*1024];

// ---------------- feature build ----------------------------------------------
__global__ void feat_mean_kernel(const float* __restrict__ hs)
{
    int bs = blockIdx.x;              // b*Ss + s
    int b = bs / Ss, s = bs % Ss;
    const float* p = hs + ((size_t)b*Ss + s)*Ee;
    size_t xb = ((size_t)s*Bb + b)*IN0v;
    float lsum = 0.f;
    for (int e = threadIdx.x; e < Ee; e += 256){
        float v = (p[e] + p[e+LSTRIDE] + p[e+2*LSTRIDE] + p[e+3*LSTRIDE])*0.25f;
        g_x0[xb + e] = v;
        lsum += v;
    }
    __shared__ float sred[256];
    sred[threadIdx.x] = lsum;
    __syncthreads();
    for (int st = 128; st > 0; st >>= 1){
        if (threadIdx.x < st) sred[threadIdx.x] += sred[threadIdx.x + st];
        __syncthreads();
    }
    if (threadIdx.x == 0) g_mw[bs] = sred[0]*(1.f/768.f);
}

__global__ void pred_kernel(const int* __restrict__ pred)
{
    int b = threadIdx.x;
    if (b >= Bb) return;
    const int* row = pred + b*Ss;
    int best = row[0], idx = 0;
    for (int s = 1; s < Ss; s++){ int v = row[s]; if (v > best){ best = v; idx = s; } }
    g_mp[b] = g_mw[b*Ss + idx];
}

__global__ void fill_kernel(const int* __restrict__ roles)
{
    int t = blockIdx.x*blockDim.x + threadIdx.x;
    if (t >= Bb*Ss) return;
    int b = t / Ss, s = t % Ss;
    int r = roles[t];
    size_t xb = ((size_t)s*Bb + b)*IN0v;
    g_x0[xb + Ee]     = g_mw[t] - g_mp[b];
    g_x0[xb + Ee + 1] = (r != 0 && r != -100) ? 1.f : 0.f;
}

// ---------------- bf16 hi/lo conversion ---------------------------------------
__global__ void convA_kernel(int srcSel, int K, int Kp)
{
    const float* A = srcSel ? g_seq0 : g_x0;
    int idx = blockIdx.x*256 + threadIdx.x;
    if (idx >= SB*Kp) return;
    int m = idx / Kp, k = idx - m*Kp;
    float v = (k < K) ? A[(size_t)m*K + k] : 0.f;
    __nv_bfloat16 h = __float2bfloat16(v);
    g_Ah[idx] = h;
    g_Al[idx] = __float2bfloat16(v - __bfloat162float(h));
}

__global__ void convW_kernel(const float* __restrict__ W, int K, int Kp, int dir)
{
    int idx = blockIdx.x*256 + threadIdx.x;
    if (idx >= Gg*Kp) return;
    int n = idx / Kp, k = idx - n*Kp;
    float v = (k < K) ? W[(size_t)n*K + k] : 0.f;
    __nv_bfloat16 h = __float2bfloat16(v);
    g_Wh[dir][idx] = h;
    g_Wl[dir][idx] = __float2bfloat16(v - __bfloat162float(h));
}

// ---------------- tensor-core GEMM  C = A*W^T + (b1+b2),  bf16x3 --------------
#define MMA16816(C, A0,A1,A2,A3, B0,B1) \
    asm volatile("mma.sync.aligned.m16n8k16.row.col.f32.bf16.bf16.f32 " \
        "{%0,%1,%2,%3}, {%4,%5,%6,%7}, {%8,%9}, {%0,%1,%2,%3};" \
        : "+f"((C)[0]),"+f"((C)[1]),"+f"((C)[2]),"+f"((C)[3]) \
        : "r"(A0),"r"(A1),"r"(A2),"r"(A3),"r"(B0),"r"(B1))

__global__ __launch_bounds__(256,2) void tc_gemm_bias(
    int dir, const float* __restrict__ b1, const float* __restrict__ b2, int Kp)
{
    __shared__ uint32_t Ah_s[128][8], Al_s[128][8];
    __shared__ uint32_t Wh_s[128][8], Wl_s[128][8];

    float* Cmat = g_xw[dir];
    const __nv_bfloat16* Whg = g_Wh[dir];
    const __nv_bfloat16* Wlg = g_Wl[dir];

    int m0 = blockIdx.y*128, n0 = blockIdx.x*128;
    int tid = threadIdx.x;
    int lane = tid & 31, wid = tid >> 5;
    int g = lane >> 2, tg = lane & 3;
    int m_w = (wid & 1)*64, n_w = (wid >> 1)*32;

    int lrow = tid >> 1, lhw = tid & 1;   // loader: row, 16B-half

    float c[4][4][4];
#pragma unroll
    for (int mi=0;mi<4;mi++)
#pragma unroll
        for (int ni=0;ni<4;ni++)
#pragma unroll
            for (int q=0;q<4;q++) c[mi][ni][q] = 0.f;

    int steps = Kp >> 4;
    for (int s = 0; s < steps; s++){
        size_t aoff = (size_t)(m0 + lrow)*Kp + s*16;
        size_t woff = (size_t)(n0 + lrow)*Kp + s*16;
        *(uint4*)&Ah_s[lrow][lhw*4] = ((const uint4*)(g_Ah + aoff))[lhw];
        *(uint4*)&Al_s[lrow][lhw*4] = ((const uint4*)(g_Al + aoff))[lhw];
        *(uint4*)&Wh_s[lrow][lhw*4] = ((const uint4*)(Whg  + woff))[lhw];
        *(uint4*)&Wl_s[lrow][lhw*4] = ((const uint4*)(Wlg  + woff))[lhw];
        __syncthreads();

        uint32_t af[4][8];
#pragma unroll
        for (int mi=0;mi<4;mi++){
            int r0 = m_w + mi*16 + g;
            af[mi][0] = Ah_s[r0  ][tg];   af[mi][1] = Ah_s[r0+8][tg];
            af[mi][2] = Ah_s[r0  ][tg+4]; af[mi][3] = Ah_s[r0+8][tg+4];
            af[mi][4] = Al_s[r0  ][tg];   af[mi][5] = Al_s[r0+8][tg];
            af[mi][6] = Al_s[r0  ][tg+4]; af[mi][7] = Al_s[r0+8][tg+4];
        }

#pragma unroll
        for (int ni=0;ni<4;ni++){
            int rn = n_w + ni*8 + g;
            uint32_t bh0 = Wh_s[rn][tg], bh1 = Wh_s[rn][tg+4];
            uint32_t bl0 = Wl_s[rn][tg], bl1 = Wl_s[rn][tg+4];
#pragma unroll
            for (int mi=0;mi<4;mi++){
                MMA16816(c[mi][ni], af[mi][0],af[mi][1],af[mi][2],af[mi][3], bh0,bh1);
                MMA16816(c[mi][ni], af[mi][0],af[mi][1],af[mi][2],af[mi][3], bl0,bl1);
                MMA16816(c[mi][ni], af[mi][4],af[mi][5],af[mi][6],af[mi][7], bh0,bh1);
            }
        }
        __syncthreads();
    }

#pragma unroll
    for (int mi=0;mi<4;mi++){
#pragma unroll
        for (int ni=0;ni<4;ni++){
            int m = m0 + m_w + mi*16 + g;
            int n = n0 + n_w + ni*8 + tg*2;
            float bb0 = b1[n] + b2[n];
            float bb1 = b1[n+1] + b2[n+1];
            float2 v0 = { c[mi][ni][0] + bb0, c[mi][ni][1] + bb1 };
            float2 v1 = { c[mi][ni][2] + bb0, c[mi][ni][3] + bb1 };
            *(float2*)&Cmat[(size_t)m*Gg + n]     = v0;
            *(float2*)&Cmat[(size_t)(m+8)*Gg + n] = v1;
        }
    }
}

// ---------------- persistent bidirectional LSTM layer (tensor-core) -----------
__device__ __forceinline__ float sigf(float x){ return 1.f/(1.f + expf(-x)); }

// R11 flat barrier (measured-good).
__device__ __forceinline__ void grid_bar(int dir, unsigned* s_gen)
{
    __syncthreads();
    if (threadIdx.x == 0){
        __threadfence();
        unsigned g0 = *s_gen;
        if (atomicAdd(&g_cnt[dir], 1u) == NCTA_DIR - 1u){
            g_cnt[dir] = 0u;
            __threadfence();
            atomicAdd(&g_gen[dir], 1u);
        } else {
            while (atomicAdd(&g_gen[dir], 0u) == g0) { __nanosleep(64); }
        }
        __threadfence();
        *s_gen = g0 + 1u;
    }
    __syncthreads();
}

// SMEM layout (bytes). A/H rows padded to 520 bf16 (260 words) -> conflict-free
// fragment LDS. red rows padded to 34 floats (EVEN stride -> float2 stores are
// 8-byte aligned; stride 33 caused the R15 misaligned-address trap).
#define AROW 520            /* bf16 per padded A/H row */
#define AROWW 260           /* words per padded row */
#define RROW 34             /* floats per red row (even!) */
#define RHALF (16*RROW)     /* 544 floats per k-half */
#define OFF_AL 16640
#define OFF_HH 33280
#define OFF_HL 66560
#define OFF_RED 99840
#define LSTM_SMEM (OFF_RED + 2*RHALF*4)   /* 104192 */

// grid = 256 CTAs (128/dir, 2/SM), 256 thr. CTA owns 4 h-cols -> 16 gate-rows.
// Per step: gates[16x32] = Whh_slice[16x512] @ h^T via mma.m16n8k16 bf16x3.
// 8 warps: ni = wid&3 (batch 8-group), kh = wid>>2 (K half). 2-way k-reduce.
__global__ __launch_bounds__(256,2) void lstm_layer_kernel(
    const float* __restrict__ Whh_f, const float* __restrict__ Whh_b, int layer)
{
    extern __shared__ char smc[];
    __nv_bfloat16* Ah_s = (__nv_bfloat16*)smc;              // [16][520]
    __nv_bfloat16* Al_s = (__nv_bfloat16*)(smc + OFF_AL);
    __nv_bfloat16* Hh_s = (__nv_bfloat16*)(smc + OFF_HH);   // [32][520]
    __nv_bfloat16* Hl_s = (__nv_bfloat16*)(smc + OFF_HL);
    float* red = (float*)(smc + OFF_RED);                   // [2][16][34]
    __shared__ unsigned s_gen;

    int dir = blockIdx.x >> 7;
    int cid = blockIdx.x & 127;
    int hc0 = cid * 4;
    int tid = threadIdx.x;
    const float* Whh = dir ? Whh_b : Whh_f;
    const float* xw  = g_xw[dir];
    float* outseq = layer ? g_seq1 : g_seq0;

    if (tid == 0) s_gen = g_gen[dir];

    // One-time: convert this CTA's 16 Whh rows (row = q*4+j <-> Whh[q*512+hc0+j])
    for (int idx = tid; idx < 16*512; idx += 256){
        int row = idx >> 9, k = idx & 511;
        int q = row >> 2, j = row & 3;
        float w = Whh[(size_t)(q*512 + hc0 + j)*512 + k];
        __nv_bfloat16 h = __float2bfloat16(w);
        Ah_s[row*AROW + k] = h;
        Al_s[row*AROW + k] = __float2bfloat16(w - __bfloat162float(h));
    }
    // zero parity-0 h (owned cols)
    if (tid < 128){
        int j = tid >> 5, b = tid & 31;
        g_hbh[dir][0][b*Hh + hc0 + j] = __float2bfloat16(0.f);
        g_hbl[dir][0][b*Hh + hc0 + j] = __float2bfloat16(0.f);
    }
    float c_reg = 0.f;                    // tid<128: cell state (h-col jj, batch bbn)
    int jj = (tid >> 5) & 3, bbn = tid & 31;

    int lane = tid & 31, wid = tid >> 5;
    int g = lane >> 2, tg = lane & 3;
    int ni = wid & 3, kh = wid >> 2;
    int nb = ni * 8;

    int xo[4];
#pragma unroll
    for (int q = 0; q < 4; q++) xo[q] = q*512 + hc0 + jj;

    grid_bar(dir, &s_gen);

    for (int t = 0; t < Ss; t++){
        int s = dir ? (Ss - 1 - t) : t;
        const float* xwt = xw + (size_t)s*Bb*Gg;

        float xpre[4] = {0.f,0.f,0.f,0.f};
        if (tid < 128){
#pragma unroll
            for (int q = 0; q < 4; q++)
                xpre[q] = __ldg(&xwt[(size_t)bbn*Gg + xo[q]]);
        }

        // stage h (parity t&1): [32][512] bf16 -> padded [32][520] smem rows
        {
            const uint4* sh = (const uint4*)&g_hbh[dir][t & 1][0];
            const uint4* sl = (const uint4*)&g_hbl[dir][t & 1][0];
#pragma unroll
            for (int r = 0; r < 8; r++){
                int idx = tid + 256*r;          // 0..2047 (64 uint4 per row)
                int row = idx >> 6, c4 = idx & 63;
                ((uint4*)((char*)Hh_s + row*(AROW*2)))[c4] = sh[idx];
                ((uint4*)((char*)Hl_s + row*(AROW*2)))[c4] = sl[idx];
            }
        }
        __syncthreads();

        // mma: warp (ni, kh) computes partial C[16 x 8] over K half
        float cacc[4] = {0.f,0.f,0.f,0.f};
        {
            const uint32_t* Ahw = (const uint32_t*)Ah_s;
            const uint32_t* Alw = (const uint32_t*)Al_s;
            const uint32_t* Hhw = (const uint32_t*)Hh_s;
            const uint32_t* Hlw = (const uint32_t*)Hl_s;
            int wb0 = kh * 128;                 // word base of this K half
            int ra0 = g*AROWW, ra1 = (g+8)*AROWW;
            int rb  = (nb + g)*AROWW;
#pragma unroll 8
            for (int ks = 0; ks < 16; ks++){
                int wb = wb0 + ks*8;
                uint32_t a0h = Ahw[ra0 + wb + tg];
                uint32_t a1h = Ahw[ra1 + wb + tg];
                uint32_t a2h = Ahw[ra0 + wb + tg + 4];
                uint32_t a3h = Ahw[ra1 + wb + tg + 4];
                uint32_t a0l = Alw[ra0 + wb + tg];
                uint32_t a1l = Alw[ra1 + wb + tg];
                uint32_t a2l = Alw[ra0 + wb + tg + 4];
                uint32_t a3l = Alw[ra1 + wb + tg + 4];
                uint32_t bh0 = Hhw[rb + wb + tg];
                uint32_t bh1 = Hhw[rb + wb + tg + 4];
                uint32_t bl0 = Hlw[rb + wb + tg];
                uint32_t bl1 = Hlw[rb + wb + tg + 4];
                MMA16816(cacc, a0h,a1h,a2h,a3h, bh0,bh1);
                MMA16816(cacc, a0h,a1h,a2h,a3h, bl0,bl1);
                MMA16816(cacc, a0l,a1l,a2l,a3l, bh0,bh1);
            }
        }
        // store partials: C frag: (row g, b nb+2tg..), (row g+8, ...)
        {
            float* rp = red + kh*RHALF;
            *(float2*)&rp[g*RROW + nb + tg*2]     = make_float2(cacc[0], cacc[1]);
            *(float2*)&rp[(g+8)*RROW + nb + tg*2] = make_float2(cacc[2], cacc[3]);
        }
        __syncthreads();

        // act phase: 2-way k-reduce + xw, gates col = q*4 + jj
        if (tid < 128){
            float pre[4];
#pragma unroll
            for (int q = 0; q < 4; q++){
                int col = q*4 + jj;
                pre[q] = red[col*RROW + bbn] + red[RHALF + col*RROW + bbn] + xpre[q];
            }
            float cnew = sigf(pre[1])*c_reg + sigf(pre[0])*tanhf(pre[2]);
            float hnew = sigf(pre[3])*tanhf(cnew);
            c_reg = cnew;
            __nv_bfloat16 hh = __float2bfloat16(hnew);
            int hb = bbn*Hh + hc0 + jj;
            g_hbh[dir][(t+1)&1][hb] = hh;
            g_hbl[dir][(t+1)&1][hb] = __float2bfloat16(hnew - __bfloat162float(hh));
            outseq[((size_t)s*Bb + bbn)*1024 + dir*512 + hc0 + jj] = hnew;
        }

        grid_bar(dir, &s_gen);
    }
}

// ---------------- output projection [8192,1024] x [1024,30] ------------------
__global__ void out_proj_kernel(const float* __restrict__ Wout,
                                const float* __restrict__ bout,
                                float* __restrict__ out)
{
    int gw = (blockIdx.x*blockDim.x + threadIdx.x) >> 5;
    int lane = threadIdx.x & 31;
    if (gw >= SB) return;
    const float* row = g_seq1 + (size_t)gw*1024;
    float xv[32];
#pragma unroll
    for (int i=0;i<32;i++) xv[i] = row[lane + 32*i];
    int s = gw >> 5, b = gw & 31;
    float* orow = out + ((size_t)b*Ss + s)*Cc;
    for (int c = 0; c < Cc; c++){
        const float* w = Wout + c*1024;
        float acc = 0.f;
#pragma unroll
        for (int i=0;i<32;i++) acc = fmaf(xv[i], w[lane + 32*i], acc);
#pragma unroll
        for (int off=16; off; off>>=1) acc += __shfl_xor_sync(0xffffffffu, acc, off);
        if (lane == 0) orow[c] = acc + bout[c];
    }
}

// ---------------- launch ------------------------------------------------------
extern "C" void kernel_launch(void* const* d_in, const int* in_sizes, int n_in,
                              void* d_out, int out_size)
{
    const float* hs     = (const float*)d_in[0];
    const int*   roles  = (const int*)  d_in[1];
    const int*   preds  = (const int*)  d_in[2];
    const float* Wih0f  = (const float*)d_in[3];
    const float* Whh0f  = (const float*)d_in[4];
    const float* bih0f  = (const float*)d_in[5];
    const float* bhh0f  = (const float*)d_in[6];
    const float* Wih0b  = (const float*)d_in[7];
    const float* Whh0b  = (const float*)d_in[8];
    const float* bih0b  = (const float*)d_in[9];
    const float* bhh0b  = (const float*)d_in[10];
    const float* Wih1f  = (const float*)d_in[11];
    const float* Whh1f  = (const float*)d_in[12];
    const float* bih1f  = (const float*)d_in[13];
    const float* bhh1f  = (const float*)d_in[14];
    const float* Wih1b  = (const float*)d_in[15];
    const float* Whh1b  = (const float*)d_in[16];
    const float* bih1b  = (const float*)d_in[17];
    const float* bhh1b  = (const float*)d_in[18];
    const float* Wout   = (const float*)d_in[19];
    const float* bout   = (const float*)d_in[20];
    float* out = (float*)d_out;

    cudaFuncSetAttribute(lstm_layer_kernel,
                         cudaFuncAttributeMaxDynamicSharedMemorySize, LSTM_SMEM);

    feat_mean_kernel<<<SB, 256>>>(hs);
    pred_kernel<<<1, 32>>>(preds);
    fill_kernel<<<(Bb*Ss + 255)/256, 256>>>(roles);

    dim3 gproj(Gg/128, SB/128);   // (16, 64)

    // ---- layer 0: Kp = 784 ----
    {
        const int K = IN0v, Kp = 784;
        convA_kernel<<<(SB*Kp + 255)/256, 256>>>(0, K, Kp);
        convW_kernel<<<(Gg*Kp + 255)/256, 256>>>(Wih0f, K, Kp, 0);
        convW_kernel<<<(Gg*Kp + 255)/256, 256>>>(Wih0b, K, Kp, 1);
        tc_gemm_bias<<<gproj, 256>>>(0, bih0f, bhh0f, Kp);
        tc_gemm_bias<<<gproj, 256>>>(1, bih0b, bhh0b, Kp);
    }
    lstm_layer_kernel<<<256, 256, LSTM_SMEM>>>(Whh0f, Whh0b, 0);

    // ---- layer 1: Kp = 1024 ----
    {
        const int K = 1024, Kp = 1024;
        convA_kernel<<<(SB*Kp + 255)/256, 256>>>(1, K, Kp);
        convW_kernel<<<(Gg*Kp + 255)/256, 256>>>(Wih1f, K, Kp, 0);
        convW_kernel<<<(Gg*Kp + 255)/256, 256>>>(Wih1b, K, Kp, 1);
        tc_gemm_bias<<<gproj, 256>>>(0, bih1f, bhh1f, Kp);
        tc_gemm_bias<<<gproj, 256>>>(1, bih1b, bhh1b, Kp);
    }
    lstm_layer_kernel<<<256, 256, LSTM_SMEM>>>(Whh1f, Whh1b, 1);

    out_proj_kernel<<<(SB*32 + 255)/256, 256>>>(Wout, bout, out);
}